// round 16
// baseline (speedup 1.0000x reference)
#include <cuda_runtime.h>

// EMA over time: y_t = 0.1*y_{t-1} + 0.9*x_t, y_{-1} = 0.
// x [B=16, T=4000, C=512] fp32 -> y same shape.
//
// Decay is 10x per step: W-step warmup rebuilds carry to 0.1^W rel error,
// so T-chunks are independent -> fully parallel streaming kernel.
//
// Store ladder (harness): __stcs 43.78 < __stwt 45.57 ~ plain 45.82 -> stcs.
// R15 isolates the READ policy: __ldcs (evict-first) tags chunk-tail lines
// for early eviction, but those exact lines are re-read by the neighbor
// chunk's warmup -> possible L2-hit loss. Default caching loads retain them
// (R2, pre-ldcs, had the best DRAM% at 73). Single variable vs R12.

static constexpr int B = 16;
static constexpr int T = 4000;
static constexpr int C = 512;
static constexpr int C4 = C / 4;        // 128 float4 lanes per (b,t) row
static constexpr int CHUNK = 20;        // 200 chunks along T -> 3200 CTAs
static constexpr int NCHUNK = T / CHUNK;
static constexpr int W = 3;             // warmup steps; 0.1^3 carry error
static constexpr int G = 5;             // timesteps per inner group

__global__ __launch_bounds__(C4) void ema_kernel(const float4* __restrict__ x,
                                                 float4* __restrict__ y) {
    const int c4 = threadIdx.x;          // 0..127
    const int chunk = blockIdx.x;        // 0..199
    const int b = blockIdx.y;            // 0..15

    const float a = 0.9f;
    const float om = 0.1f;

    const int t0 = chunk * CHUNK;
    const size_t base = (size_t)b * T * C4 + c4;

    float4 acc = make_float4(0.f, 0.f, 0.f, 0.f);

    // Warmup: rebuild carry from up to W steps back (first chunk has none).
    // These lines were just streamed by the neighbor chunk -> L2 hits if
    // the main pass didn't mark them evict-first.
    if (t0 >= W) {
        size_t widx = base + (size_t)(t0 - W) * C4;
        float4 v[W];
        #pragma unroll
        for (int t = 0; t < W; ++t) v[t] = x[widx + (size_t)t * C4];
        #pragma unroll
        for (int t = 0; t < W; ++t) {
            acc.x = fmaf(om, acc.x, a * v[t].x);
            acc.y = fmaf(om, acc.y, a * v[t].y);
            acc.z = fmaf(om, acc.z, a * v[t].z);
            acc.w = fmaf(om, acc.w, a * v[t].w);
        }
    }

    // Main chunk: G-wide load batches (default caching -> tail lines stay
    // in L2 for the neighbor's warmup), FMA chain, __stcs streaming stores.
    size_t idx = base + (size_t)t0 * C4;
    for (int g = 0; g < CHUNK / G; ++g) {
        float4 v[G];
        #pragma unroll
        for (int t = 0; t < G; ++t) v[t] = x[idx + (size_t)t * C4];
        #pragma unroll
        for (int t = 0; t < G; ++t) {
            acc.x = fmaf(om, acc.x, a * v[t].x);
            acc.y = fmaf(om, acc.y, a * v[t].y);
            acc.z = fmaf(om, acc.z, a * v[t].z);
            acc.w = fmaf(om, acc.w, a * v[t].w);
            v[t] = acc;
        }
        #pragma unroll
        for (int t = 0; t < G; ++t)
            __stcs(&y[idx + (size_t)t * C4], v[t]);
        idx += (size_t)G * C4;
    }
}

extern "C" void kernel_launch(void* const* d_in, const int* in_sizes, int n_in,
                              void* d_out, int out_size) {
    const float4* x = (const float4*)d_in[0];
    float4* y = (float4*)d_out;
    dim3 grid(NCHUNK, B);
    dim3 block(C4);
    ema_kernel<<<grid, block>>>(x, y);
}

// round 17
// speedup vs baseline: 1.0618x; 1.0618x over previous
#include <cuda_runtime.h>

// EMA over time: y_t = 0.1*y_{t-1} + 0.9*x_t, y_{-1} = 0.
// x [B=16, T=4000, C=512] fp32 -> y same shape.
//
// Decay is 10x per step: W-step warmup rebuilds carry to 0.1^W rel error,
// so T-chunks are independent -> fully parallel streaming kernel.
//
// Validated by single-variable ladders (harness us):
//   stores: __stcs 43.78 < __stwt 45.57 ~ plain 45.82
//   loads:  __ldcs 43.78 < default 46.21
//   -> evict-fast on both streams; kernel sits at mixed-R/W HBM roofline.
// R17: CHUNK 20->25 with W=3 cuts warmup read amplification to 1.12x
// (vs 1.15x at CHUNK=20, 1.16x at R7's W=4) with all policies pinned.

static constexpr int B = 16;
static constexpr int T = 4000;
static constexpr int C = 512;
static constexpr int C4 = C / 4;        // 128 float4 lanes per (b,t) row
static constexpr int CHUNK = 25;        // 160 chunks along T -> 2560 CTAs
static constexpr int NCHUNK = T / CHUNK;
static constexpr int W = 3;             // warmup steps; 0.1^3 carry error
static constexpr int G = 5;             // timesteps per inner group

__global__ __launch_bounds__(C4) void ema_kernel(const float4* __restrict__ x,
                                                 float4* __restrict__ y) {
    const int c4 = threadIdx.x;          // 0..127
    const int chunk = blockIdx.x;        // 0..159
    const int b = blockIdx.y;            // 0..15

    const float a = 0.9f;
    const float om = 0.1f;

    const int t0 = chunk * CHUNK;
    const size_t base = (size_t)b * T * C4 + c4;

    float4 acc = make_float4(0.f, 0.f, 0.f, 0.f);

    // Warmup: rebuild carry from up to W steps back (first chunk has none).
    // These lines are streamed concurrently by the neighbor chunk -> L2 hits.
    if (t0 >= W) {
        size_t widx = base + (size_t)(t0 - W) * C4;
        float4 v[W];
        #pragma unroll
        for (int t = 0; t < W; ++t) v[t] = x[widx + (size_t)t * C4];
        #pragma unroll
        for (int t = 0; t < W; ++t) {
            acc.x = fmaf(om, acc.x, a * v[t].x);
            acc.y = fmaf(om, acc.y, a * v[t].y);
            acc.z = fmaf(om, acc.z, a * v[t].z);
            acc.w = fmaf(om, acc.w, a * v[t].w);
        }
    }

    // Main chunk: G-wide evict-first load batches, FMA chain, streaming stores.
    size_t idx = base + (size_t)t0 * C4;
    for (int g = 0; g < CHUNK / G; ++g) {
        float4 v[G];
        #pragma unroll
        for (int t = 0; t < G; ++t) v[t] = __ldcs(&x[idx + (size_t)t * C4]);
        #pragma unroll
        for (int t = 0; t < G; ++t) {
            acc.x = fmaf(om, acc.x, a * v[t].x);
            acc.y = fmaf(om, acc.y, a * v[t].y);
            acc.z = fmaf(om, acc.z, a * v[t].z);
            acc.w = fmaf(om, acc.w, a * v[t].w);
            v[t] = acc;
        }
        #pragma unroll
        for (int t = 0; t < G; ++t)
            __stcs(&y[idx + (size_t)t * C4], v[t]);
        idx += (size_t)G * C4;
    }
}

extern "C" void kernel_launch(void* const* d_in, const int* in_sizes, int n_in,
                              void* d_out, int out_size) {
    const float4* x = (const float4*)d_in[0];
    float4* y = (float4*)d_out;
    dim3 grid(NCHUNK, B);
    dim3 block(C4);
    ema_kernel<<<grid, block>>>(x, y);
}